// round 1
// baseline (speedup 1.0000x reference)
#include <cuda_runtime.h>
#include <cstdint>

#define BB   8192
#define KK   64
#define DD   384
#define HH   64
#define TOPK 8
#define NPAIR 28

// triu_indices(8, k=1), row-major
__device__ __constant__ int c_ii[NPAIR] =
  {0,0,0,0,0,0,0, 1,1,1,1,1,1, 2,2,2,2,2, 3,3,3,3, 4,4,4, 5,5, 6};
__device__ __constant__ int c_jj[NPAIR] =
  {1,2,3,4,5,6,7, 2,3,4,5,6,7, 3,4,5,6,7, 4,5,6,7, 5,6,7, 6,7, 7};

__device__ __forceinline__ float silu(float x) {
    return x / (1.0f + __expf(-x));
}

__global__ __launch_bounds__(128, 8)
void rpe_kernel(const float* __restrict__ M,
                const float* __restrict__ y,
                const float* __restrict__ ts,
                const float* __restrict__ W1,
                const float* __restrict__ b1,
                const float* __restrict__ W2,
                const float* __restrict__ b2,
                const float* __restrict__ W3,
                const float* __restrict__ b3,
                float* __restrict__ out)
{
    __shared__ float sy[KK];
    __shared__ float st[KK];
    __shared__ float sm[TOPK][DD];      // gathered top-8 M rows
    __shared__ float su[TOPK][128];     // u[k][h]: h<64 -> m_k@W1a col h ; h>=64 -> m_k@W1b col h-64
    __shared__ float sW2[HH * 32];
    __shared__ float s_wdt[HH], s_wyi[HH], s_wyj[HH], s_b1[HH];
    __shared__ float s_b2[32], s_W3[32];
    __shared__ int   s_idx[TOPK];
    __shared__ float s_ty[TOPK], s_tt[TOPK];
    __shared__ float s_h1[4][HH];
    __shared__ float s_wpart[4];
    __shared__ float s_b3;

    const int b    = blockIdx.x;
    const int tid  = threadIdx.x;
    const int lane = tid & 31;
    const int wid  = tid >> 5;

    // ---- stage small inputs / weights into smem ----
    if (tid < KK) {
        sy[tid] = y[(size_t)b * KK + tid];
        st[tid] = ts[(size_t)b * KK + tid];
    }
    for (int i = tid; i < HH * 32; i += 128) sW2[i] = W2[i];
    if (tid < HH) {
        s_wdt[tid] = W1[768 * 64 + tid];
        s_wyi[tid] = W1[769 * 64 + tid];
        s_wyj[tid] = W1[770 * 64 + tid];
        s_b1[tid]  = b1[tid];
    }
    if (tid < 32) { s_b2[tid] = b2[tid]; s_W3[tid] = W3[tid]; }
    if (tid == 0) s_b3 = b3[0];
    __syncthreads();

    // ---- top-8 selection (warp 0), matching jax.lax.top_k semantics:
    // descending by value, ties -> lower index first.
    // y in [0,1) so raw float bits are monotone; pack (bits<<32)|(63-idx).
    if (wid == 0) {
        unsigned long long k0 =
            ((unsigned long long)__float_as_uint(sy[lane]) << 32) | (unsigned)(63 - lane);
        unsigned long long k1 =
            ((unsigned long long)__float_as_uint(sy[lane + 32]) << 32) | (unsigned)(63 - (lane + 32));
        #pragma unroll
        for (int t = 0; t < TOPK; t++) {
            unsigned long long m = (k0 > k1) ? k0 : k1;
            #pragma unroll
            for (int off = 16; off > 0; off >>= 1) {
                unsigned long long o = __shfl_xor_sync(0xffffffffu, m, off);
                if (o > m) m = o;
            }
            int idx = 63 - (int)(m & 63ull);
            if (idx == lane)      k0 = 0ull;
            if (idx == lane + 32) k1 = 0ull;
            if (lane == 0) {
                s_idx[t] = idx;
                s_ty[t]  = sy[idx];
                s_tt[t]  = st[idx];
            }
        }
    }
    __syncthreads();

    // ---- gather top-8 M rows into smem (vectorized float4) ----
    {
        // 8 rows * 96 float4 = 768 float4 loads
        for (int e = tid; e < TOPK * (DD / 4); e += 128) {
            int k = e / (DD / 4);
            int q = e - k * (DD / 4);
            const float4* src = reinterpret_cast<const float4*>(
                M + ((size_t)b * KK + s_idx[k]) * DD);
            reinterpret_cast<float4*>(&sm[k][0])[q] = src[q];
        }
    }
    __syncthreads();

    // ---- layer 1 shared part: u[k][col] = sum_d m_k[d] * W1col[d] ----
    // col < 64  : W1[d][col]        (m_i half)
    // col >= 64 : W1[384+d][col-64] (m_j half)
    {
        const int col = tid;
        const float* wptr = (col < 64) ? (W1 + col)
                                       : (W1 + 384 * 64 + (col - 64));
        float acc[TOPK] = {0.f, 0.f, 0.f, 0.f, 0.f, 0.f, 0.f, 0.f};
        for (int d = 0; d < DD; d += 4) {
            float w0 = wptr[(d + 0) * 64];
            float w1 = wptr[(d + 1) * 64];
            float w2 = wptr[(d + 2) * 64];
            float w3 = wptr[(d + 3) * 64];
            #pragma unroll
            for (int k = 0; k < TOPK; k++) {
                float4 m4 = *reinterpret_cast<const float4*>(&sm[k][d]);
                acc[k] = fmaf(m4.x, w0, acc[k]);
                acc[k] = fmaf(m4.y, w1, acc[k]);
                acc[k] = fmaf(m4.z, w2, acc[k]);
                acc[k] = fmaf(m4.w, w3, acc[k]);
            }
        }
        #pragma unroll
        for (int k = 0; k < TOPK; k++) su[k][col] = acc[k];
    }
    __syncthreads();

    // ---- 28 pairs: assemble layer-1 from u, then MLP layers 2 & 3 ----
    float wsum = 0.f;
    for (int p = wid; p < NPAIR; p += 4) {
        const int i = c_ii[p], j = c_jj[p];
        const float dt = s_tt[i] - s_tt[j];
        const float yi = s_ty[i], yj = s_ty[j];

        // h1: 64 values, 2 per lane
        {
            int h = lane;
            float pre = su[i][h] + su[j][64 + h]
                      + dt * s_wdt[h] + yi * s_wyi[h] + yj * s_wyj[h] + s_b1[h];
            s_h1[wid][h] = silu(pre);
            h = lane + 32;
            pre = su[i][h] + su[j][64 + h]
                + dt * s_wdt[h] + yi * s_wyi[h] + yj * s_wyj[h] + s_b1[h];
            s_h1[wid][h] = silu(pre);
        }
        __syncwarp();

        // h2[lane] = silu(h1 @ W2 + b2), one output per lane
        float a2 = s_b2[lane];
        #pragma unroll
        for (int h = 0; h < HH; h++)
            a2 = fmaf(s_h1[wid][h], sW2[h * 32 + lane], a2);
        float h2 = silu(a2);

        // penalty = h2 @ W3 + b3 (warp reduce)
        float v = h2 * s_W3[lane];
        #pragma unroll
        for (int off = 16; off > 0; off >>= 1)
            v += __shfl_xor_sync(0xffffffffu, v, off);
        if (lane == 0) wsum += (v + s_b3) * yi * yj;
        __syncwarp();
    }

    if (lane == 0) s_wpart[wid] = wsum;
    __syncthreads();
    if (tid == 0)
        out[b] = s_wpart[0] + s_wpart[1] + s_wpart[2] + s_wpart[3];
}

extern "C" void kernel_launch(void* const* d_in, const int* in_sizes, int n_in,
                              void* d_out, int out_size)
{
    const float* M  = (const float*)d_in[0];
    const float* y  = (const float*)d_in[1];
    const float* ts = (const float*)d_in[2];
    const float* W1 = (const float*)d_in[3];
    const float* b1 = (const float*)d_in[4];
    const float* W2 = (const float*)d_in[5];
    const float* b2 = (const float*)d_in[6];
    const float* W3 = (const float*)d_in[7];
    const float* b3 = (const float*)d_in[8];
    float* out = (float*)d_out;

    rpe_kernel<<<BB, 128>>>(M, y, ts, W1, b1, W2, b2, W3, b3, out);
}

// round 3
// speedup vs baseline: 1.1232x; 1.1232x over previous
#include <cuda_runtime.h>
#include <cuda_bf16.h>
#include <cstdint>

#define BB   8192
#define KK   64
#define DD   384
#define TOPK 8
#define NPAIR 28
#define BPB  16       // batches per block
#define NT   256      // 8 warps
#define SB   136      // row stride in bf16 units
#define SBB  272      // row stride in bytes (conflict-free for ldmatrix)
#define SUSTRIDE 132  // u staging stride (floats)

#define OFF_AHI 0
#define OFF_ALO 34816
#define OFF_WHI 69632
#define OFF_WLO 104448
#define DYN_BYTES 139264

// triu_indices(8, k=1)
__device__ __constant__ int c_ii[NPAIR] =
  {0,0,0,0,0,0,0, 1,1,1,1,1,1, 2,2,2,2,2, 3,3,3,3, 4,4,4, 5,5, 6};
__device__ __constant__ int c_jj[NPAIR] =
  {1,2,3,4,5,6,7, 2,3,4,5,6,7, 3,4,5,6,7, 4,5,6,7, 5,6,7, 6,7, 7};

__device__ __forceinline__ uint32_t smem_u32(const void* p) {
    uint32_t a;
    asm("{ .reg .u64 t; cvta.to.shared.u64 t, %1; cvt.u32.u64 %0, t; }"
        : "=r"(a) : "l"(p));
    return a;
}
__device__ __forceinline__ float silu(float x) { return x / (1.0f + __expf(-x)); }

__device__ __forceinline__ void ldm_x4(uint32_t addr, uint32_t& r0, uint32_t& r1,
                                       uint32_t& r2, uint32_t& r3) {
    asm volatile("ldmatrix.sync.aligned.m8n8.x4.shared.b16 {%0,%1,%2,%3}, [%4];"
        : "=r"(r0), "=r"(r1), "=r"(r2), "=r"(r3) : "r"(addr));
}
__device__ __forceinline__ void ldm_x4t(uint32_t addr, uint32_t& r0, uint32_t& r1,
                                        uint32_t& r2, uint32_t& r3) {
    asm volatile("ldmatrix.sync.aligned.m8n8.x4.trans.shared.b16 {%0,%1,%2,%3}, [%4];"
        : "=r"(r0), "=r"(r1), "=r"(r2), "=r"(r3) : "r"(addr));
}
__device__ __forceinline__ void mma_bf16(float* c, const uint32_t* a,
                                         uint32_t b0, uint32_t b1) {
    asm volatile(
        "mma.sync.aligned.m16n8k16.row.col.f32.bf16.bf16.f32 "
        "{%0,%1,%2,%3}, {%4,%5,%6,%7}, {%8,%9}, {%0,%1,%2,%3};"
        : "+f"(c[0]), "+f"(c[1]), "+f"(c[2]), "+f"(c[3])
        : "r"(a[0]), "r"(a[1]), "r"(a[2]), "r"(a[3]), "r"(b0), "r"(b1));
}
// split fp32 pair into packed bf16 hi and residual lo
__device__ __forceinline__ void split2(float a, float b, uint32_t& hi, uint32_t& lo) {
    __nv_bfloat16 ha = __float2bfloat16(a), hb = __float2bfloat16(b);
    __nv_bfloat16 la = __float2bfloat16(a - __bfloat162float(ha));
    __nv_bfloat16 lb = __float2bfloat16(b - __bfloat162float(hb));
    hi = ((uint32_t)__bfloat16_as_ushort(hb) << 16) | __bfloat16_as_ushort(ha);
    lo = ((uint32_t)__bfloat16_as_ushort(lb) << 16) | __bfloat16_as_ushort(la);
}

__global__ __launch_bounds__(NT, 1)
void rpe_hmma_kernel(const float* __restrict__ M,
                     const float* __restrict__ y,
                     const float* __restrict__ ts,
                     const float* __restrict__ W1,
                     const float* __restrict__ b1,
                     const float* __restrict__ W2,
                     const float* __restrict__ b2,
                     const float* __restrict__ W3,
                     const float* __restrict__ b3,
                     float* __restrict__ out)
{
    extern __shared__ __align__(128) char dyn[];

    __shared__ __align__(16) float sy[BPB][KK];
    __shared__ __align__(16) float st_[BPB][KK];
    __shared__ float s_ty[BPB][TOPK], s_tt[BPB][TOPK];
    __shared__ int   s_idx[BPB][TOPK];
    __shared__ __align__(16) float sW2[64 * 32];
    __shared__ float s_wdt[64], s_wyi[64], s_wyj[64], s_b1[64];
    __shared__ float s_b2[32], s_W3[32];
    __shared__ float s_b3;

    const int tid  = threadIdx.x;
    const int lane = tid & 31;
    const int wid  = tid >> 5;
    const int b0   = blockIdx.x * BPB;
    const uint32_t dynu = smem_u32(dyn);

    // ---- stage small inputs / weights ----
    {
        const float4* ysrc = (const float4*)(y  + (size_t)b0 * KK);
        const float4* tsrc = (const float4*)(ts + (size_t)b0 * KK);
        ((float4*)sy)[tid]  = ysrc[tid];
        ((float4*)st_)[tid] = tsrc[tid];
    }
    for (int i = tid; i < 64 * 32; i += NT) sW2[i] = W2[i];
    if (tid < 64) {
        s_wdt[tid] = W1[768 * 64 + tid];
        s_wyi[tid] = W1[769 * 64 + tid];
        s_wyj[tid] = W1[770 * 64 + tid];
        s_b1[tid]  = b1[tid];
    }
    if (tid < 32) { s_b2[tid] = b2[tid]; s_W3[tid] = W3[tid]; }
    if (tid == 0) s_b3 = b3[0];
    __syncthreads();

    // ---- per-warp top-8 for 2 batches (jax.lax.top_k semantics: desc, ties->low idx) ----
    for (int lb = wid * 2; lb < wid * 2 + 2; lb++) {
        unsigned long long k0 =
            ((unsigned long long)__float_as_uint(sy[lb][lane]) << 32) | (unsigned)(63 - lane);
        unsigned long long k1 =
            ((unsigned long long)__float_as_uint(sy[lb][lane + 32]) << 32) | (unsigned)(63 - (lane + 32));
        #pragma unroll
        for (int t = 0; t < TOPK; t++) {
            unsigned long long m = (k0 > k1) ? k0 : k1;
            #pragma unroll
            for (int off = 16; off > 0; off >>= 1) {
                unsigned long long o = __shfl_xor_sync(0xffffffffu, m, off);
                if (o > m) m = o;
            }
            int idx = 63 - (int)(m & 63ull);
            if (idx == lane)      k0 = 0ull;
            if (idx == lane + 32) k1 = 0ull;
            if (lane == 0) {
                s_idx[lb][t] = idx;
                s_ty[lb][t]  = sy[lb][idx];
                s_tt[lb][t]  = st_[lb][idx];
            }
        }
    }
    __syncthreads();

    // ---- GEMM: u[128][128] = A[128][384] @ W'[384][128], bf16x3 via mma.sync ----
    const int wm = wid & 3;        // m-tile: rows wm*32 .. +32
    const int wn = wid >> 2;       // n-tile: cols wn*64 .. +64
    const uint32_t a_row = (uint32_t)((lane & 7) + ((lane >> 3) & 1) * 8);
    const uint32_t a_kof = (uint32_t)((lane >> 4) * 8);
    const uint32_t b_kof = (uint32_t)((lane & 7) + ((lane >> 3) & 1) * 8);
    const uint32_t b_nof = (uint32_t)((lane >> 4) * 8);

    float acc[2][8][4];
    #pragma unroll
    for (int t = 0; t < 2; t++)
        #pragma unroll
        for (int j = 0; j < 8; j++)
            #pragma unroll
            for (int r = 0; r < 4; r++) acc[t][j][r] = 0.f;

    for (int chunk = 0; chunk < 3; chunk++) {
        // A fill: 128 rows x 128 fp32 cols -> bf16 hi/lo, layout [m][k] stride SB
        #pragma unroll
        for (int i = 0; i < 16; i++) {
            int idx4 = i * NT + tid;          // float4 index, 0..4095
            int row  = idx4 >> 5;             // 0..127
            int q    = idx4 & 31;             // float4 within 128-col chunk
            int lb = row >> 3, slot = row & 7;
            const float4 v = *(const float4*)(
                M + ((size_t)(b0 + lb) * KK + s_idx[lb][slot]) * DD + chunk * 128 + q * 4);
            uint2 hp, lp;
            split2(v.x, v.y, hp.x, lp.x);
            split2(v.z, v.w, hp.y, lp.y);
            uint32_t off = (uint32_t)row * SBB + (uint32_t)q * 8;
            *(uint2*)(dyn + OFF_AHI + off) = hp;
            *(uint2*)(dyn + OFF_ALO + off) = lp;
        }
        // W fill: layout [k][n] stride SB; n<64 -> W1[g][n] (m_i), n>=64 -> W1[384+g][n-64]
        {
            int k    = tid >> 1;              // 0..127
            int half = tid & 1;
            int g    = (half ? 384 : 0) + chunk * 128 + k;
            const float4* wp = (const float4*)(W1 + (size_t)g * 64);
            #pragma unroll
            for (int c4 = 0; c4 < 16; c4++) {
                float4 w = wp[c4];
                uint2 hp, lp;
                split2(w.x, w.y, hp.x, lp.x);
                split2(w.z, w.w, hp.y, lp.y);
                uint32_t off = (uint32_t)k * SBB + (uint32_t)(half * 64 + c4 * 4) * 2;
                *(uint2*)(dyn + OFF_WHI + off) = hp;
                *(uint2*)(dyn + OFF_WLO + off) = lp;
            }
        }
        __syncthreads();

        // 3 passes: (Ahi,Whi), (Ahi,Wlo), (Alo,Whi)
        #pragma unroll
        for (int pass = 0; pass < 3; pass++) {
            const uint32_t abase = dynu + (pass == 2 ? OFF_ALO : OFF_AHI);
            const uint32_t wbase = dynu + (pass == 1 ? OFF_WLO : OFF_WHI);
            #pragma unroll
            for (int step = 0; step < 8; step++) {
                const uint32_t k0 = (uint32_t)step * 16;
                uint32_t afr[2][4];
                #pragma unroll
                for (int t = 0; t < 2; t++)
                    ldm_x4(abase + (wm * 32 + t * 16 + a_row) * SBB + (k0 + a_kof) * 2,
                           afr[t][0], afr[t][1], afr[t][2], afr[t][3]);
                uint32_t bfr[8][2];
                #pragma unroll
                for (int q = 0; q < 4; q++) {
                    uint32_t r0, r1, r2, r3;
                    ldm_x4t(wbase + (k0 + b_kof) * SBB + (wn * 64 + q * 16 + b_nof) * 2,
                            r0, r1, r2, r3);
                    bfr[q * 2][0] = r0;     bfr[q * 2][1] = r1;
                    bfr[q * 2 + 1][0] = r2; bfr[q * 2 + 1][1] = r3;
                }
                #pragma unroll
                for (int t = 0; t < 2; t++)
                    #pragma unroll
                    for (int j = 0; j < 8; j++)
                        mma_bf16(acc[t][j], afr[t], bfr[j][0], bfr[j][1]);
            }
        }
        __syncthreads();
    }

    // ---- writeback C -> su[128][SUSTRIDE] (reuses dynamic smem) ----
    float* su = (float*)dyn;
    #pragma unroll
    for (int t = 0; t < 2; t++) {
        int m = wm * 32 + t * 16 + (lane >> 2);
        #pragma unroll
        for (int j = 0; j < 8; j++) {
            int n = wn * 64 + j * 8 + (lane & 3) * 2;
            su[m * SUSTRIDE + n]           = acc[t][j][0];
            su[m * SUSTRIDE + n + 1]       = acc[t][j][1];
            su[(m + 8) * SUSTRIDE + n]     = acc[t][j][2];
            su[(m + 8) * SUSTRIDE + n + 1] = acc[t][j][3];
        }
    }
    __syncthreads();

    // ---- pair phase: W2 in registers, shuffle-based layer 2 ----
    float w2r[64];
    #pragma unroll
    for (int h = 0; h < 64; h++) w2r[h] = sW2[h * 32 + lane];
    const float b2v = s_b2[lane];
    const float w3v = s_W3[lane];
    const float b3v = s_b3;

    for (int lb = wid * 2; lb < wid * 2 + 2; lb++) {
        const int r0 = lb * TOPK;
        float acc_out = 0.f;
        #pragma unroll 4
        for (int p = 0; p < NPAIR; p++) {
            const int i = c_ii[p], j = c_jj[p];
            const float dt = s_tt[lb][i] - s_tt[lb][j];
            const float yi = s_ty[lb][i], yj = s_ty[lb][j];

            float pre_lo = su[(r0 + i) * SUSTRIDE + lane]
                         + su[(r0 + j) * SUSTRIDE + 64 + lane]
                         + dt * s_wdt[lane] + yi * s_wyi[lane] + yj * s_wyj[lane]
                         + s_b1[lane];
            float pre_hi = su[(r0 + i) * SUSTRIDE + 32 + lane]
                         + su[(r0 + j) * SUSTRIDE + 96 + lane]
                         + dt * s_wdt[32 + lane] + yi * s_wyi[32 + lane]
                         + yj * s_wyj[32 + lane] + s_b1[32 + lane];
            float h1a = silu(pre_lo);
            float h1b = silu(pre_hi);

            float s0 = 0.f, s1 = 0.f, s2 = 0.f, s3 = 0.f;
            #pragma unroll
            for (int hh = 0; hh < 32; hh += 4) {
                s0 = fmaf(__shfl_sync(0xffffffffu, h1a, hh),     w2r[hh],     s0);
                s1 = fmaf(__shfl_sync(0xffffffffu, h1a, hh + 1), w2r[hh + 1], s1);
                s2 = fmaf(__shfl_sync(0xffffffffu, h1a, hh + 2), w2r[hh + 2], s2);
                s3 = fmaf(__shfl_sync(0xffffffffu, h1a, hh + 3), w2r[hh + 3], s3);
            }
            #pragma unroll
            for (int hh = 0; hh < 32; hh += 4) {
                s0 = fmaf(__shfl_sync(0xffffffffu, h1b, hh),     w2r[32 + hh],     s0);
                s1 = fmaf(__shfl_sync(0xffffffffu, h1b, hh + 1), w2r[32 + hh + 1], s1);
                s2 = fmaf(__shfl_sync(0xffffffffu, h1b, hh + 2), w2r[32 + hh + 2], s2);
                s3 = fmaf(__shfl_sync(0xffffffffu, h1b, hh + 3), w2r[32 + hh + 3], s3);
            }
            float a2 = b2v + (s0 + s1) + (s2 + s3);

            float v = silu(a2) * w3v;
            #pragma unroll
            for (int off = 16; off > 0; off >>= 1)
                v += __shfl_xor_sync(0xffffffffu, v, off);
            if (lane == 0) acc_out += (v + b3v) * yi * yj;
        }
        if (lane == 0) out[b0 + lb] = acc_out;
    }
}

extern "C" void kernel_launch(void* const* d_in, const int* in_sizes, int n_in,
                              void* d_out, int out_size)
{
    const float* M  = (const float*)d_in[0];
    const float* y  = (const float*)d_in[1];
    const float* ts = (const float*)d_in[2];
    const float* W1 = (const float*)d_in[3];
    const float* b1 = (const float*)d_in[4];
    const float* W2 = (const float*)d_in[5];
    const float* b2 = (const float*)d_in[6];
    const float* W3 = (const float*)d_in[7];
    const float* b3 = (const float*)d_in[8];
    float* out = (float*)d_out;

    cudaFuncSetAttribute(rpe_hmma_kernel,
                         cudaFuncAttributeMaxDynamicSharedMemorySize, DYN_BYTES);
    rpe_hmma_kernel<<<BB / BPB, NT, DYN_BYTES>>>(M, y, ts, W1, b1, W2, b2, W3, b3, out);
}

// round 4
// speedup vs baseline: 1.5675x; 1.3956x over previous
#include <cuda_runtime.h>
#include <cuda_bf16.h>
#include <cstdint>

#define BB   8192
#define KK   64
#define DD   384
#define TOPK 8
#define NPAIR 28
#define BPB  16       // batches per block
#define NT   512      // 16 warps
#define SBB  272      // tile row stride in bytes (conflict-free ldmatrix)
#define SUSTRIDE 132  // u staging stride (floats)

#define OFF_AHI 0
#define OFF_ALO 34816
#define OFF_WHI 69632
#define OFF_WLO 104448
#define DYN_BYTES 139264

// Pre-converted W1 in smem-tile layout: [chunk][k][n], row stride 136 bf16 = 272B
__device__ __align__(16) __nv_bfloat16 g_W1H[3][128][136];
__device__ __align__(16) __nv_bfloat16 g_W1L[3][128][136];

// triu_indices(8, k=1)
__device__ __constant__ int c_ii[NPAIR] =
  {0,0,0,0,0,0,0, 1,1,1,1,1,1, 2,2,2,2,2, 3,3,3,3, 4,4,4, 5,5, 6};
__device__ __constant__ int c_jj[NPAIR] =
  {1,2,3,4,5,6,7, 2,3,4,5,6,7, 3,4,5,6,7, 4,5,6,7, 5,6,7, 6,7, 7};

__device__ __forceinline__ uint32_t smem_u32(const void* p) {
    uint32_t a;
    asm("{ .reg .u64 t; cvta.to.shared.u64 t, %1; cvt.u32.u64 %0, t; }"
        : "=r"(a) : "l"(p));
    return a;
}
__device__ __forceinline__ float silu(float x) { return x / (1.0f + __expf(-x)); }

__device__ __forceinline__ void ldm_x4(uint32_t addr, uint32_t& r0, uint32_t& r1,
                                       uint32_t& r2, uint32_t& r3) {
    asm volatile("ldmatrix.sync.aligned.m8n8.x4.shared.b16 {%0,%1,%2,%3}, [%4];"
        : "=r"(r0), "=r"(r1), "=r"(r2), "=r"(r3) : "r"(addr));
}
__device__ __forceinline__ void ldm_x4t(uint32_t addr, uint32_t& r0, uint32_t& r1,
                                        uint32_t& r2, uint32_t& r3) {
    asm volatile("ldmatrix.sync.aligned.m8n8.x4.trans.shared.b16 {%0,%1,%2,%3}, [%4];"
        : "=r"(r0), "=r"(r1), "=r"(r2), "=r"(r3) : "r"(addr));
}
__device__ __forceinline__ void mma_bf16(float* c, const uint32_t* a,
                                         uint32_t b0, uint32_t b1) {
    asm volatile(
        "mma.sync.aligned.m16n8k16.row.col.f32.bf16.bf16.f32 "
        "{%0,%1,%2,%3}, {%4,%5,%6,%7}, {%8,%9}, {%0,%1,%2,%3};"
        : "+f"(c[0]), "+f"(c[1]), "+f"(c[2]), "+f"(c[3])
        : "r"(a[0]), "r"(a[1]), "r"(a[2]), "r"(a[3]), "r"(b0), "r"(b1));
}
__device__ __forceinline__ void split2(float a, float b, uint32_t& hi, uint32_t& lo) {
    __nv_bfloat16 ha = __float2bfloat16(a), hb = __float2bfloat16(b);
    __nv_bfloat16 la = __float2bfloat16(a - __bfloat162float(ha));
    __nv_bfloat16 lb = __float2bfloat16(b - __bfloat162float(hb));
    hi = ((uint32_t)__bfloat16_as_ushort(hb) << 16) | __bfloat16_as_ushort(ha);
    lo = ((uint32_t)__bfloat16_as_ushort(lb) << 16) | __bfloat16_as_ushort(la);
}

// ---- prep: convert W1 -> bf16 hi/lo tiles, once ----
__global__ void w1_prep_kernel(const float* __restrict__ W1)
{
    int idx = blockIdx.x * blockDim.x + threadIdx.x;   // 0..49151
    int chunk = idx >> 14;
    int k     = (idx >> 7) & 127;
    int n     = idx & 127;
    int g     = ((n >= 64) ? 384 : 0) + chunk * 128 + k;
    float v = W1[(size_t)g * 64 + (n & 63)];
    __nv_bfloat16 h = __float2bfloat16(v);
    __nv_bfloat16 l = __float2bfloat16(v - __bfloat162float(h));
    g_W1H[chunk][k][n] = h;
    g_W1L[chunk][k][n] = l;
}

__global__ __launch_bounds__(NT, 1)
void rpe_hmma_kernel(const float* __restrict__ M,
                     const float* __restrict__ y,
                     const float* __restrict__ ts,
                     const float* __restrict__ W1,
                     const float* __restrict__ b1,
                     const float* __restrict__ W2,
                     const float* __restrict__ b2,
                     const float* __restrict__ W3,
                     const float* __restrict__ b3,
                     float* __restrict__ out)
{
    extern __shared__ __align__(128) char dyn[];

    __shared__ __align__(16) float sy[BPB][KK];
    __shared__ __align__(16) float st_[BPB][KK];
    __shared__ float s_ty[BPB][TOPK], s_tt[BPB][TOPK];
    __shared__ int   s_idx[BPB][TOPK];
    __shared__ __align__(16) float sW2[64 * 32];
    __shared__ float s_wdt[64], s_wyi[64], s_wyj[64], s_b1[64];
    __shared__ float s_b2[32], s_W3[32];
    __shared__ float s_b3;
    __shared__ __align__(16) float s_h1b[16][32];

    const int tid  = threadIdx.x;
    const int lane = tid & 31;
    const int wid  = tid >> 5;
    const int b0   = blockIdx.x * BPB;
    const uint32_t dynu = smem_u32(dyn);

    // ---- stage small inputs / weights ----
    if (tid < 256) {
        const float4* ysrc = (const float4*)(y  + (size_t)b0 * KK);
        const float4* tsrc = (const float4*)(ts + (size_t)b0 * KK);
        ((float4*)sy)[tid]  = ysrc[tid];
        ((float4*)st_)[tid] = tsrc[tid];
    }
    for (int i = tid; i < 64 * 32; i += NT) sW2[i] = W2[i];
    if (tid < 64) {
        s_wdt[tid] = W1[768 * 64 + tid];
        s_wyi[tid] = W1[769 * 64 + tid];
        s_wyj[tid] = W1[770 * 64 + tid];
        s_b1[tid]  = b1[tid];
    }
    if (tid < 32) { s_b2[tid] = b2[tid]; s_W3[tid] = W3[tid]; }
    if (tid == 0) s_b3 = b3[0];
    __syncthreads();

    // ---- per-warp top-8, one batch per warp (jax.lax.top_k semantics) ----
    {
        const int lb = wid;
        unsigned long long k0 =
            ((unsigned long long)__float_as_uint(sy[lb][lane]) << 32) | (unsigned)(63 - lane);
        unsigned long long k1 =
            ((unsigned long long)__float_as_uint(sy[lb][lane + 32]) << 32) | (unsigned)(63 - (lane + 32));
        #pragma unroll
        for (int t = 0; t < TOPK; t++) {
            unsigned long long m = (k0 > k1) ? k0 : k1;
            #pragma unroll
            for (int off = 16; off > 0; off >>= 1) {
                unsigned long long o = __shfl_xor_sync(0xffffffffu, m, off);
                if (o > m) m = o;
            }
            int idx = 63 - (int)(m & 63ull);
            if (idx == lane)      k0 = 0ull;
            if (idx == lane + 32) k1 = 0ull;
            if (lane == 0) {
                s_idx[lb][t] = idx;
                s_ty[lb][t]  = sy[lb][idx];
                s_tt[lb][t]  = st_[lb][idx];
            }
        }
    }
    __syncthreads();

    // ---- GEMM: u[128][128] = A[128][384] @ W'[384][128], bf16x3 via mma.sync ----
    const int wm = wid & 3;        // m-tile: rows wm*32 .. +32
    const int wn = wid >> 2;       // n-tile: cols wn*32 .. +32
    const uint32_t a_row = (uint32_t)((lane & 7) + ((lane >> 3) & 1) * 8);
    const uint32_t a_kof = (uint32_t)((lane >> 4) * 8);
    const uint32_t b_kof = (uint32_t)((lane & 7) + ((lane >> 3) & 1) * 8);
    const uint32_t b_nof = (uint32_t)((lane >> 4) * 8);

    float acc[2][4][4];
    #pragma unroll
    for (int t = 0; t < 2; t++)
        #pragma unroll
        for (int j = 0; j < 4; j++)
            #pragma unroll
            for (int r = 0; r < 4; r++) acc[t][j][r] = 0.f;

    for (int chunk = 0; chunk < 3; chunk++) {
        // A fill: gather + split to bf16 hi/lo, [m][k] layout, stride 272B
        #pragma unroll
        for (int i = 0; i < 8; i++) {
            int idx4 = i * NT + tid;          // 0..4095 float4 units
            int row  = idx4 >> 5;             // 0..127
            int q    = idx4 & 31;
            int lb = row >> 3, slot = row & 7;
            const float4 v = *(const float4*)(
                M + ((size_t)(b0 + lb) * KK + s_idx[lb][slot]) * DD + chunk * 128 + q * 4);
            uint2 hp, lp;
            split2(v.x, v.y, hp.x, lp.x);
            split2(v.z, v.w, hp.y, lp.y);
            uint32_t off = (uint32_t)row * SBB + (uint32_t)q * 8;
            *(uint2*)(dyn + OFF_AHI + off) = hp;
            *(uint2*)(dyn + OFF_ALO + off) = lp;
        }
        // W fill: straight uint4 copy from pre-converted globals (same layout)
        {
            const uint4* srcH = (const uint4*)&g_W1H[chunk][0][0];
            const uint4* srcL = (const uint4*)&g_W1L[chunk][0][0];
            uint4* dstH = (uint4*)(dyn + OFF_WHI);
            uint4* dstL = (uint4*)(dyn + OFF_WLO);
            #pragma unroll
            for (int i = tid; i < 2176; i += NT) {
                dstH[i] = srcH[i];
                dstL[i] = srcL[i];
            }
        }
        __syncthreads();

        // 3 passes: (Ahi,Whi), (Ahi,Wlo), (Alo,Whi)
        #pragma unroll
        for (int pass = 0; pass < 3; pass++) {
            const uint32_t abase = dynu + (pass == 2 ? OFF_ALO : OFF_AHI);
            const uint32_t wbase = dynu + (pass == 1 ? OFF_WLO : OFF_WHI);
            #pragma unroll
            for (int step = 0; step < 8; step++) {
                const uint32_t k0 = (uint32_t)step * 16;
                uint32_t afr[2][4];
                #pragma unroll
                for (int t = 0; t < 2; t++)
                    ldm_x4(abase + (wm * 32 + t * 16 + a_row) * SBB + (k0 + a_kof) * 2,
                           afr[t][0], afr[t][1], afr[t][2], afr[t][3]);
                uint32_t bfr[4][2];
                #pragma unroll
                for (int q = 0; q < 2; q++) {
                    uint32_t r0, r1, r2, r3;
                    ldm_x4t(wbase + (k0 + b_kof) * SBB + (wn * 32 + q * 16 + b_nof) * 2,
                            r0, r1, r2, r3);
                    bfr[q * 2][0] = r0;     bfr[q * 2][1] = r1;
                    bfr[q * 2 + 1][0] = r2; bfr[q * 2 + 1][1] = r3;
                }
                #pragma unroll
                for (int t = 0; t < 2; t++)
                    #pragma unroll
                    for (int j = 0; j < 4; j++)
                        mma_bf16(acc[t][j], afr[t], bfr[j][0], bfr[j][1]);
            }
        }
        __syncthreads();
    }

    // ---- writeback C -> su[128][SUSTRIDE] (reuses dynamic smem) ----
    float* su = (float*)dyn;
    #pragma unroll
    for (int t = 0; t < 2; t++) {
        int m = wm * 32 + t * 16 + (lane >> 2);
        #pragma unroll
        for (int j = 0; j < 4; j++) {
            int n = wn * 32 + j * 8 + (lane & 3) * 2;
            su[m * SUSTRIDE + n]           = acc[t][j][0];
            su[m * SUSTRIDE + n + 1]       = acc[t][j][1];
            su[(m + 8) * SUSTRIDE + n]     = acc[t][j][2];
            su[(m + 8) * SUSTRIDE + n + 1] = acc[t][j][3];
        }
    }
    __syncthreads();

    // ---- pair phase: one batch per warp; W2 in regs; shfl + LDS split ----
    float w2r[64];
    #pragma unroll
    for (int h = 0; h < 64; h++) w2r[h] = sW2[h * 32 + lane];
    const float b2v = s_b2[lane];
    const float w3v = s_W3[lane];
    const float b3v = s_b3;

    {
        const int lb = wid;
        const int r0 = lb * TOPK;
        float acc_out = 0.f;
        #pragma unroll 4
        for (int p = 0; p < NPAIR; p++) {
            const int i = c_ii[p], j = c_jj[p];
            const float dt = s_tt[lb][i] - s_tt[lb][j];
            const float yi = s_ty[lb][i], yj = s_ty[lb][j];

            float pre_lo = su[(r0 + i) * SUSTRIDE + lane]
                         + su[(r0 + j) * SUSTRIDE + 64 + lane]
                         + dt * s_wdt[lane] + yi * s_wyi[lane] + yj * s_wyj[lane]
                         + s_b1[lane];
            float pre_hi = su[(r0 + i) * SUSTRIDE + 32 + lane]
                         + su[(r0 + j) * SUSTRIDE + 96 + lane]
                         + dt * s_wdt[32 + lane] + yi * s_wyi[32 + lane]
                         + yj * s_wyj[32 + lane] + s_b1[32 + lane];
            float h1a = silu(pre_lo);
            float h1b = silu(pre_hi);

            s_h1b[lb][lane] = h1b;
            __syncwarp();

            float s0 = 0.f, s1 = 0.f, s2 = 0.f, s3 = 0.f;
            // h 0..31 via shuffle (MIO pipe)
            #pragma unroll
            for (int hh = 0; hh < 32; hh += 4) {
                s0 = fmaf(__shfl_sync(0xffffffffu, h1a, hh),     w2r[hh],     s0);
                s1 = fmaf(__shfl_sync(0xffffffffu, h1a, hh + 1), w2r[hh + 1], s1);
                s2 = fmaf(__shfl_sync(0xffffffffu, h1a, hh + 2), w2r[hh + 2], s2);
                s3 = fmaf(__shfl_sync(0xffffffffu, h1a, hh + 3), w2r[hh + 3], s3);
            }
            // h 32..63 via float4 smem broadcast (LSU pipe)
            #pragma unroll
            for (int c4 = 0; c4 < 8; c4++) {
                float4 hv = *(const float4*)&s_h1b[lb][c4 * 4];
                s0 = fmaf(hv.x, w2r[32 + c4 * 4 + 0], s0);
                s1 = fmaf(hv.y, w2r[32 + c4 * 4 + 1], s1);
                s2 = fmaf(hv.z, w2r[32 + c4 * 4 + 2], s2);
                s3 = fmaf(hv.w, w2r[32 + c4 * 4 + 3], s3);
            }
            float a2 = b2v + (s0 + s1) + (s2 + s3);

            float v = silu(a2) * w3v;
            #pragma unroll
            for (int off = 16; off > 0; off >>= 1)
                v += __shfl_xor_sync(0xffffffffu, v, off);
            if (lane == 0) acc_out += (v + b3v) * yi * yj;
            __syncwarp();
        }
        if (lane == 0) out[b0 + lb] = acc_out;
    }
}

extern "C" void kernel_launch(void* const* d_in, const int* in_sizes, int n_in,
                              void* d_out, int out_size)
{
    const float* M  = (const float*)d_in[0];
    const float* y  = (const float*)d_in[1];
    const float* ts = (const float*)d_in[2];
    const float* W1 = (const float*)d_in[3];
    const float* b1 = (const float*)d_in[4];
    const float* W2 = (const float*)d_in[5];
    const float* b2 = (const float*)d_in[6];
    const float* W3 = (const float*)d_in[7];
    const float* b3 = (const float*)d_in[8];
    float* out = (float*)d_out;

    w1_prep_kernel<<<96, 512>>>(W1);
    cudaFuncSetAttribute(rpe_hmma_kernel,
                         cudaFuncAttributeMaxDynamicSharedMemorySize, DYN_BYTES);
    rpe_hmma_kernel<<<BB / BPB, NT, DYN_BYTES>>>(M, y, ts, W1, b1, W2, b2, W3, b3, out);
}

// round 5
// speedup vs baseline: 1.6923x; 1.0796x over previous
#include <cuda_runtime.h>
#include <cuda_bf16.h>
#include <cstdint>

#define BB   8192
#define KK   64
#define DD   384
#define TOPK 8
#define NPAIR 28
#define BPB  8        // batches per gemm block
#define NT   256      // 8 warps
#define SBB  272      // tile row stride bytes (conflict-free ldmatrix)

#define OFF_AHI 0
#define OFF_ALO 17408
#define OFF_WHI 34816
#define OFF_WLO 69632
#define DYN_BYTES 104448

// Pre-converted W1 tiles: [chunk][k][n], row stride 136 bf16 = 272B
__device__ __align__(16) __nv_bfloat16 g_W1H[3][128][136];
__device__ __align__(16) __nv_bfloat16 g_W1L[3][128][136];
// Inter-kernel scratch
__device__ __align__(16) float g_u[BB * TOPK * 128];   // 33.5MB, L2-resident
__device__ float g_ty[BB * TOPK];
__device__ float g_tt[BB * TOPK];

// triu_indices(8, k=1)
__device__ __constant__ int c_ii[NPAIR] =
  {0,0,0,0,0,0,0, 1,1,1,1,1,1, 2,2,2,2,2, 3,3,3,3, 4,4,4, 5,5, 6};
__device__ __constant__ int c_jj[NPAIR] =
  {1,2,3,4,5,6,7, 2,3,4,5,6,7, 3,4,5,6,7, 4,5,6,7, 5,6,7, 6,7, 7};

__device__ __forceinline__ uint32_t smem_u32(const void* p) {
    uint32_t a;
    asm("{ .reg .u64 t; cvta.to.shared.u64 t, %1; cvt.u32.u64 %0, t; }"
        : "=r"(a) : "l"(p));
    return a;
}
__device__ __forceinline__ float silu(float x) { return x / (1.0f + __expf(-x)); }

__device__ __forceinline__ void ldm_x4(uint32_t addr, uint32_t& r0, uint32_t& r1,
                                       uint32_t& r2, uint32_t& r3) {
    asm volatile("ldmatrix.sync.aligned.m8n8.x4.shared.b16 {%0,%1,%2,%3}, [%4];"
        : "=r"(r0), "=r"(r1), "=r"(r2), "=r"(r3) : "r"(addr));
}
__device__ __forceinline__ void ldm_x4t(uint32_t addr, uint32_t& r0, uint32_t& r1,
                                        uint32_t& r2, uint32_t& r3) {
    asm volatile("ldmatrix.sync.aligned.m8n8.x4.trans.shared.b16 {%0,%1,%2,%3}, [%4];"
        : "=r"(r0), "=r"(r1), "=r"(r2), "=r"(r3) : "r"(addr));
}
__device__ __forceinline__ void mma_bf16(float* c, const uint32_t* a,
                                         uint32_t b0, uint32_t b1) {
    asm volatile(
        "mma.sync.aligned.m16n8k16.row.col.f32.bf16.bf16.f32 "
        "{%0,%1,%2,%3}, {%4,%5,%6,%7}, {%8,%9}, {%0,%1,%2,%3};"
        : "+f"(c[0]), "+f"(c[1]), "+f"(c[2]), "+f"(c[3])
        : "r"(a[0]), "r"(a[1]), "r"(a[2]), "r"(a[3]), "r"(b0), "r"(b1));
}
__device__ __forceinline__ void split2(float a, float b, uint32_t& hi, uint32_t& lo) {
    __nv_bfloat16 ha = __float2bfloat16(a), hb = __float2bfloat16(b);
    __nv_bfloat16 la = __float2bfloat16(a - __bfloat162float(ha));
    __nv_bfloat16 lb = __float2bfloat16(b - __bfloat162float(hb));
    hi = ((uint32_t)__bfloat16_as_ushort(hb) << 16) | __bfloat16_as_ushort(ha);
    lo = ((uint32_t)__bfloat16_as_ushort(lb) << 16) | __bfloat16_as_ushort(la);
}
__device__ __forceinline__ void cp_async16(uint32_t dst, const void* src) {
    asm volatile("cp.async.cg.shared.global [%0], [%1], 16;" :: "r"(dst), "l"(src));
}

// ---- prep: convert W1 -> bf16 hi/lo tiles, once ----
__global__ void w1_prep_kernel(const float* __restrict__ W1)
{
    int idx = blockIdx.x * blockDim.x + threadIdx.x;   // 0..49151
    int chunk = idx >> 14;
    int k     = (idx >> 7) & 127;
    int n     = idx & 127;
    int g     = ((n >= 64) ? 384 : 0) + chunk * 128 + k;
    float v = W1[(size_t)g * 64 + (n & 63)];
    __nv_bfloat16 h = __float2bfloat16(v);
    __nv_bfloat16 l = __float2bfloat16(v - __bfloat162float(h));
    g_W1H[chunk][k][n] = h;
    g_W1L[chunk][k][n] = l;
}

// ============ kernel 1: topk + layer-1 GEMM -> g_u ============
__global__ __launch_bounds__(NT, 2)
void rpe_gemm_kernel(const float* __restrict__ M,
                     const float* __restrict__ y,
                     const float* __restrict__ ts)
{
    extern __shared__ __align__(128) char dyn[];

    __shared__ __align__(16) float sy[BPB][KK];
    __shared__ __align__(16) float st_[BPB][KK];
    __shared__ int s_idx[BPB][TOPK];

    const int tid  = threadIdx.x;
    const int lane = tid & 31;
    const int wid  = tid >> 5;
    const int b0   = blockIdx.x * BPB;
    const uint32_t dynu = smem_u32(dyn);

    // stage y/ts
    if (tid < 128) {
        ((float4*)sy)[tid]  = ((const float4*)(y  + (size_t)b0 * KK))[tid];
        ((float4*)st_)[tid] = ((const float4*)(ts + (size_t)b0 * KK))[tid];
    }
    __syncthreads();

    // per-warp top-8 (jax.lax.top_k semantics: desc, ties->low idx)
    {
        const int lb = wid;
        unsigned long long k0 =
            ((unsigned long long)__float_as_uint(sy[lb][lane]) << 32) | (unsigned)(63 - lane);
        unsigned long long k1 =
            ((unsigned long long)__float_as_uint(sy[lb][lane + 32]) << 32) | (unsigned)(63 - (lane + 32));
        #pragma unroll
        for (int t = 0; t < TOPK; t++) {
            unsigned long long m = (k0 > k1) ? k0 : k1;
            #pragma unroll
            for (int off = 16; off > 0; off >>= 1) {
                unsigned long long o = __shfl_xor_sync(0xffffffffu, m, off);
                if (o > m) m = o;
            }
            int idx = 63 - (int)(m & 63ull);
            if (idx == lane)      k0 = 0ull;
            if (idx == lane + 32) k1 = 0ull;
            if (lane == 0) {
                s_idx[lb][t] = idx;
                g_ty[(size_t)(b0 + lb) * TOPK + t] = sy[lb][idx];
                g_tt[(size_t)(b0 + lb) * TOPK + t] = st_[lb][idx];
            }
        }
    }
    __syncthreads();

    // GEMM: u[64][128] = A[64][384] @ W'[384][128], bf16x3
    const int wm = wid & 1;       // m-tile: rows wm*32..+32
    const int wn = wid >> 1;      // n-tile: cols wn*32..+32
    const uint32_t a_row = (uint32_t)((lane & 7) + ((lane >> 3) & 1) * 8);
    const uint32_t a_kof = (uint32_t)((lane >> 4) * 8);
    const uint32_t b_kof = (uint32_t)((lane & 7) + ((lane >> 3) & 1) * 8);
    const uint32_t b_nof = (uint32_t)((lane >> 4) * 8);

    float acc[2][4][4];
    #pragma unroll
    for (int t = 0; t < 2; t++)
        #pragma unroll
        for (int j = 0; j < 4; j++)
            #pragma unroll
            for (int r = 0; r < 4; r++) acc[t][j][r] = 0.f;

    for (int chunk = 0; chunk < 3; chunk++) {
        // W copy via cp.async (pure bytes, pre-converted)
        {
            const uint4* srcH = (const uint4*)&g_W1H[chunk][0][0];
            const uint4* srcL = (const uint4*)&g_W1L[chunk][0][0];
            #pragma unroll
            for (int i = tid; i < 2176; i += NT) {
                cp_async16(dynu + OFF_WHI + i * 16, srcH + i);
                cp_async16(dynu + OFF_WLO + i * 16, srcL + i);
            }
            asm volatile("cp.async.commit_group;" ::: "memory");
        }
        // A fill: gather + split bf16 hi/lo, [m][k] stride 272B
        #pragma unroll
        for (int i = 0; i < 8; i++) {
            int idx4 = i * NT + tid;        // 0..2047 float4 units
            int row  = idx4 >> 5;           // 0..63
            int q    = idx4 & 31;
            int lb = row >> 3, slot = row & 7;
            const float4 v = *(const float4*)(
                M + ((size_t)(b0 + lb) * KK + s_idx[lb][slot]) * DD + chunk * 128 + q * 4);
            uint2 hp, lp;
            split2(v.x, v.y, hp.x, lp.x);
            split2(v.z, v.w, hp.y, lp.y);
            uint32_t off = (uint32_t)row * SBB + (uint32_t)q * 8;
            *(uint2*)(dyn + OFF_AHI + off) = hp;
            *(uint2*)(dyn + OFF_ALO + off) = lp;
        }
        asm volatile("cp.async.wait_group 0;" ::: "memory");
        __syncthreads();

        // 3 passes: (Ahi,Whi), (Ahi,Wlo), (Alo,Whi)
        #pragma unroll
        for (int pass = 0; pass < 3; pass++) {
            const uint32_t abase = dynu + (pass == 2 ? OFF_ALO : OFF_AHI);
            const uint32_t wbase = dynu + (pass == 1 ? OFF_WLO : OFF_WHI);
            #pragma unroll
            for (int step = 0; step < 8; step++) {
                const uint32_t k0 = (uint32_t)step * 16;
                uint32_t afr[2][4];
                #pragma unroll
                for (int t = 0; t < 2; t++)
                    ldm_x4(abase + (wm * 32 + t * 16 + a_row) * SBB + (k0 + a_kof) * 2,
                           afr[t][0], afr[t][1], afr[t][2], afr[t][3]);
                uint32_t bfr[4][2];
                #pragma unroll
                for (int q = 0; q < 2; q++) {
                    uint32_t r0, r1, r2, r3;
                    ldm_x4t(wbase + (k0 + b_kof) * SBB + (wn * 32 + q * 16 + b_nof) * 2,
                            r0, r1, r2, r3);
                    bfr[q * 2][0] = r0;     bfr[q * 2][1] = r1;
                    bfr[q * 2 + 1][0] = r2; bfr[q * 2 + 1][1] = r3;
                }
                #pragma unroll
                for (int t = 0; t < 2; t++)
                    #pragma unroll
                    for (int j = 0; j < 4; j++)
                        mma_bf16(acc[t][j], afr[t], bfr[j][0], bfr[j][1]);
            }
        }
        __syncthreads();
    }

    // direct STG of accumulators to g_u (32B-sector aligned across lanes)
    #pragma unroll
    for (int t = 0; t < 2; t++) {
        int m = wm * 32 + t * 16 + (lane >> 2);
        #pragma unroll
        for (int j = 0; j < 4; j++) {
            int n = wn * 32 + j * 8 + (lane & 3) * 2;
            *(float2*)&g_u[((size_t)b0 * TOPK + m) * 128 + n] =
                make_float2(acc[t][j][0], acc[t][j][1]);
            *(float2*)&g_u[((size_t)b0 * TOPK + m + 8) * 128 + n] =
                make_float2(acc[t][j][2], acc[t][j][3]);
        }
    }
}

// ============ kernel 2: pair-phase MLP ============
__global__ __launch_bounds__(NT, 2)
void rpe_pair_kernel(const float* __restrict__ W1,
                     const float* __restrict__ b1,
                     const float* __restrict__ W2,
                     const float* __restrict__ b2,
                     const float* __restrict__ W3,
                     const float* __restrict__ b3,
                     float* __restrict__ out)
{
    __shared__ __align__(16) float sW2[64 * 32];
    __shared__ float s_wdt[64], s_wyi[64], s_wyj[64], s_b1[64];
    __shared__ float s_b2[32], s_W3[32];
    __shared__ float s_b3;
    __shared__ __align__(16) float s_h1b[8][32];

    const int tid  = threadIdx.x;
    const int lane = tid & 31;
    const int wid  = tid >> 5;
    const int b    = blockIdx.x * 8 + wid;

    for (int i = tid; i < 512; i += NT)
        ((float4*)sW2)[i] = ((const float4*)W2)[i];
    if (tid < 64) {
        s_wdt[tid] = W1[768 * 64 + tid];
        s_wyi[tid] = W1[769 * 64 + tid];
        s_wyj[tid] = W1[770 * 64 + tid];
        s_b1[tid]  = b1[tid];
    }
    if (tid < 32) { s_b2[tid] = b2[tid]; s_W3[tid] = W3[tid]; }
    if (tid == 0) s_b3 = b3[0];
    __syncthreads();

    // prefetch u[b] into regs: ur[row][g] = u[b][row][g*32+lane]
    float ur[TOPK][4];
    #pragma unroll
    for (int r = 0; r < TOPK; r++)
        #pragma unroll
        for (int g = 0; g < 4; g++)
            ur[r][g] = g_u[((size_t)b * TOPK + r) * 128 + g * 32 + lane];

    const float tyl = g_ty[(size_t)b * TOPK + (lane & 7)];
    const float ttl = g_tt[(size_t)b * TOPK + (lane & 7)];

    float w2r[64];
    #pragma unroll
    for (int h = 0; h < 64; h++) w2r[h] = sW2[h * 32 + lane];
    const float b2v = s_b2[lane];
    const float w3v = s_W3[lane];
    const float b3v = s_b3;

    float acc_out = 0.f;
    #pragma unroll 4
    for (int p = 0; p < NPAIR; p++) {
        const int i = c_ii[p], j = c_jj[p];
        const float ti = __shfl_sync(0xffffffffu, ttl, i);
        const float tj = __shfl_sync(0xffffffffu, ttl, j);
        const float yi = __shfl_sync(0xffffffffu, tyl, i);
        const float yj = __shfl_sync(0xffffffffu, tyl, j);
        const float dt = ti - tj;

        float pre_lo = ur[i][0] + ur[j][2]
                     + dt * s_wdt[lane] + yi * s_wyi[lane] + yj * s_wyj[lane]
                     + s_b1[lane];
        float pre_hi = ur[i][1] + ur[j][3]
                     + dt * s_wdt[32 + lane] + yi * s_wyi[32 + lane]
                     + yj * s_wyj[32 + lane] + s_b1[32 + lane];
        float h1a = silu(pre_lo);
        float h1b = silu(pre_hi);

        s_h1b[wid][lane] = h1b;
        __syncwarp();

        float s0 = 0.f, s1 = 0.f, s2 = 0.f, s3 = 0.f;
        #pragma unroll
        for (int hh = 0; hh < 32; hh += 4) {
            s0 = fmaf(__shfl_sync(0xffffffffu, h1a, hh),     w2r[hh],     s0);
            s1 = fmaf(__shfl_sync(0xffffffffu, h1a, hh + 1), w2r[hh + 1], s1);
            s2 = fmaf(__shfl_sync(0xffffffffu, h1a, hh + 2), w2r[hh + 2], s2);
            s3 = fmaf(__shfl_sync(0xffffffffu, h1a, hh + 3), w2r[hh + 3], s3);
        }
        #pragma unroll
        for (int c4 = 0; c4 < 8; c4++) {
            float4 hv = *(const float4*)&s_h1b[wid][c4 * 4];
            s0 = fmaf(hv.x, w2r[32 + c4 * 4 + 0], s0);
            s1 = fmaf(hv.y, w2r[32 + c4 * 4 + 1], s1);
            s2 = fmaf(hv.z, w2r[32 + c4 * 4 + 2], s2);
            s3 = fmaf(hv.w, w2r[32 + c4 * 4 + 3], s3);
        }
        float a2 = b2v + (s0 + s1) + (s2 + s3);

        float v = silu(a2) * w3v;
        #pragma unroll
        for (int off = 16; off > 0; off >>= 1)
            v += __shfl_xor_sync(0xffffffffu, v, off);
        if (lane == 0) acc_out += (v + b3v) * yi * yj;
        __syncwarp();
    }
    if (lane == 0) out[b] = acc_out;
}

extern "C" void kernel_launch(void* const* d_in, const int* in_sizes, int n_in,
                              void* d_out, int out_size)
{
    const float* M  = (const float*)d_in[0];
    const float* y  = (const float*)d_in[1];
    const float* ts = (const float*)d_in[2];
    const float* W1 = (const float*)d_in[3];
    const float* b1 = (const float*)d_in[4];
    const float* W2 = (const float*)d_in[5];
    const float* b2 = (const float*)d_in[6];
    const float* W3 = (const float*)d_in[7];
    const float* b3 = (const float*)d_in[8];
    float* out = (float*)d_out;

    w1_prep_kernel<<<96, 512>>>(W1);
    cudaFuncSetAttribute(rpe_gemm_kernel,
                         cudaFuncAttributeMaxDynamicSharedMemorySize, DYN_BYTES);
    rpe_gemm_kernel<<<BB / BPB, NT, DYN_BYTES>>>(M, y, ts);
    rpe_pair_kernel<<<BB / 8, NT>>>(W1, b1, W2, b2, W3, b3, out);
}

// round 6
// speedup vs baseline: 1.9222x; 1.1358x over previous
#include <cuda_runtime.h>
#include <cuda_bf16.h>
#include <cstdint>

#define BB   8192
#define KK   64
#define DD   384
#define TOPK 8
#define NPAIR 28
#define BPB  8        // batches per gemm block
#define NT   256      // 8 warps
#define SBB  272      // tile row stride bytes (conflict-free ldmatrix)

#define OFF_AHI 0
#define OFF_ALO 17408
#define OFF_WHI 34816
#define OFF_WLO 69632
#define DYN_BYTES 104448

// Pre-converted W1 tiles: [chunk][k][n], row stride 136 bf16 = 272B
__device__ __align__(16) __nv_bfloat16 g_W1H[3][128][136];
__device__ __align__(16) __nv_bfloat16 g_W1L[3][128][136];
// Inter-kernel scratch
__device__ __align__(16) float g_u[BB * TOPK * 128];   // 33.5MB
__device__ float g_ty[BB * TOPK];
__device__ float g_tt[BB * TOPK];

// triu_indices(8, k=1)
__device__ __constant__ int c_ii[NPAIR] =
  {0,0,0,0,0,0,0, 1,1,1,1,1,1, 2,2,2,2,2, 3,3,3,3, 4,4,4, 5,5, 6};
__device__ __constant__ int c_jj[NPAIR] =
  {1,2,3,4,5,6,7, 2,3,4,5,6,7, 3,4,5,6,7, 4,5,6,7, 5,6,7, 6,7, 7};

__device__ __forceinline__ uint32_t smem_u32(const void* p) {
    uint32_t a;
    asm("{ .reg .u64 t; cvta.to.shared.u64 t, %1; cvt.u32.u64 %0, t; }"
        : "=r"(a) : "l"(p));
    return a;
}
__device__ __forceinline__ float silu(float x) { return x / (1.0f + __expf(-x)); }

__device__ __forceinline__ void ldm_x4(uint32_t addr, uint32_t* r) {
    asm volatile("ldmatrix.sync.aligned.m8n8.x4.shared.b16 {%0,%1,%2,%3}, [%4];"
        : "=r"(r[0]), "=r"(r[1]), "=r"(r[2]), "=r"(r[3]) : "r"(addr));
}
__device__ __forceinline__ void ldm_x4t(uint32_t addr, uint32_t& r0, uint32_t& r1,
                                        uint32_t& r2, uint32_t& r3) {
    asm volatile("ldmatrix.sync.aligned.m8n8.x4.trans.shared.b16 {%0,%1,%2,%3}, [%4];"
        : "=r"(r0), "=r"(r1), "=r"(r2), "=r"(r3) : "r"(addr));
}
__device__ __forceinline__ void mma_bf16(float* c, const uint32_t* a,
                                         uint32_t b0, uint32_t b1) {
    asm volatile(
        "mma.sync.aligned.m16n8k16.row.col.f32.bf16.bf16.f32 "
        "{%0,%1,%2,%3}, {%4,%5,%6,%7}, {%8,%9}, {%0,%1,%2,%3};"
        : "+f"(c[0]), "+f"(c[1]), "+f"(c[2]), "+f"(c[3])
        : "r"(a[0]), "r"(a[1]), "r"(a[2]), "r"(a[3]), "r"(b0), "r"(b1));
}
// packed split: hi = bf16x2{b,a}, lo = bf16x2 of residuals (RN, identical to scalar path)
__device__ __forceinline__ void split2(float a, float b, uint32_t& hi, uint32_t& lo) {
    asm("cvt.rn.bf16x2.f32 %0, %1, %2;" : "=r"(hi) : "f"(b), "f"(a));
    float ra = __uint_as_float(hi << 16);
    float rb = __uint_as_float(hi & 0xffff0000u);
    float la = a - ra;
    float lb = b - rb;
    asm("cvt.rn.bf16x2.f32 %0, %1, %2;" : "=r"(lo) : "f"(lb), "f"(la));
}
__device__ __forceinline__ void cp_async16(uint32_t dst, const void* src) {
    asm volatile("cp.async.cg.shared.global [%0], [%1], 16;" :: "r"(dst), "l"(src));
}

// ---- prep: convert W1 -> bf16 hi/lo tiles, once ----
__global__ void w1_prep_kernel(const float* __restrict__ W1)
{
    int idx = blockIdx.x * blockDim.x + threadIdx.x;   // 0..49151
    int chunk = idx >> 14;
    int k     = (idx >> 7) & 127;
    int n     = idx & 127;
    int g     = ((n >= 64) ? 384 : 0) + chunk * 128 + k;
    float v = W1[(size_t)g * 64 + (n & 63)];
    __nv_bfloat16 h = __float2bfloat16(v);
    __nv_bfloat16 l = __float2bfloat16(v - __bfloat162float(h));
    g_W1H[chunk][k][n] = h;
    g_W1L[chunk][k][n] = l;
}

// ============ kernel 1: topk + layer-1 GEMM -> g_u ============
__global__ __launch_bounds__(NT, 2)
void rpe_gemm_kernel(const float* __restrict__ M,
                     const float* __restrict__ y,
                     const float* __restrict__ ts)
{
    extern __shared__ __align__(128) char dyn[];

    __shared__ __align__(16) float sy[BPB][KK];
    __shared__ __align__(16) float st_[BPB][KK];
    __shared__ int s_idx[BPB][TOPK];

    const int tid  = threadIdx.x;
    const int lane = tid & 31;
    const int wid  = tid >> 5;
    const int b0   = blockIdx.x * BPB;
    const uint32_t dynu = smem_u32(dyn);

    if (tid < 128) {
        ((float4*)sy)[tid]  = ((const float4*)(y  + (size_t)b0 * KK))[tid];
        ((float4*)st_)[tid] = ((const float4*)(ts + (size_t)b0 * KK))[tid];
    }
    __syncthreads();

    // per-warp top-8 (jax.lax.top_k semantics: desc, ties->low idx)
    {
        const int lb = wid;
        unsigned long long k0 =
            ((unsigned long long)__float_as_uint(sy[lb][lane]) << 32) | (unsigned)(63 - lane);
        unsigned long long k1 =
            ((unsigned long long)__float_as_uint(sy[lb][lane + 32]) << 32) | (unsigned)(63 - (lane + 32));
        #pragma unroll
        for (int t = 0; t < TOPK; t++) {
            unsigned long long m = (k0 > k1) ? k0 : k1;
            #pragma unroll
            for (int off = 16; off > 0; off >>= 1) {
                unsigned long long o = __shfl_xor_sync(0xffffffffu, m, off);
                if (o > m) m = o;
            }
            int idx = 63 - (int)(m & 63ull);
            if (idx == lane)      k0 = 0ull;
            if (idx == lane + 32) k1 = 0ull;
            if (lane == 0) {
                s_idx[lb][t] = idx;
                g_ty[(size_t)(b0 + lb) * TOPK + t] = sy[lb][idx];
                g_tt[(size_t)(b0 + lb) * TOPK + t] = st_[lb][idx];
            }
        }
    }
    __syncthreads();

    // GEMM: u[64][128] = A[64][384] @ W'[384][128], bf16x3 with fragment reuse
    const int wm = wid & 1;
    const int wn = wid >> 1;
    const uint32_t a_row = (uint32_t)((lane & 7) + ((lane >> 3) & 1) * 8);
    const uint32_t a_kof = (uint32_t)((lane >> 4) * 8);
    const uint32_t b_kof = (uint32_t)((lane & 7) + ((lane >> 3) & 1) * 8);
    const uint32_t b_nof = (uint32_t)((lane >> 4) * 8);

    float acc[2][4][4];
    #pragma unroll
    for (int t = 0; t < 2; t++)
        #pragma unroll
        for (int j = 0; j < 4; j++)
            #pragma unroll
            for (int r = 0; r < 4; r++) acc[t][j][r] = 0.f;

    for (int chunk = 0; chunk < 3; chunk++) {
        // W copy via cp.async (pre-converted)
        {
            const uint4* srcH = (const uint4*)&g_W1H[chunk][0][0];
            const uint4* srcL = (const uint4*)&g_W1L[chunk][0][0];
            #pragma unroll
            for (int i = tid; i < 2176; i += NT) {
                cp_async16(dynu + OFF_WHI + i * 16, srcH + i);
                cp_async16(dynu + OFF_WLO + i * 16, srcL + i);
            }
            asm volatile("cp.async.commit_group;" ::: "memory");
        }
        // A fill: gather + packed split, [m][k] stride 272B
        #pragma unroll
        for (int i = 0; i < 8; i++) {
            int idx4 = i * NT + tid;
            int row  = idx4 >> 5;
            int q    = idx4 & 31;
            int lb = row >> 3, slot = row & 7;
            const float4 v = *(const float4*)(
                M + ((size_t)(b0 + lb) * KK + s_idx[lb][slot]) * DD + chunk * 128 + q * 4);
            uint2 hp, lp;
            split2(v.x, v.y, hp.x, lp.x);
            split2(v.z, v.w, hp.y, lp.y);
            uint32_t off = (uint32_t)row * SBB + (uint32_t)q * 8;
            *(uint2*)(dyn + OFF_AHI + off) = hp;
            *(uint2*)(dyn + OFF_ALO + off) = lp;
        }
        asm volatile("cp.async.wait_group 0;" ::: "memory");
        __syncthreads();

        // per k16 step: load all frags once, issue the 3 bf16x3 products
        #pragma unroll
        for (int step = 0; step < 8; step++) {
            const uint32_t k0 = (uint32_t)step * 16;
            const uint32_t a_off = (wm * 32 + a_row) * SBB + (k0 + a_kof) * 2;
            const uint32_t b_off = (k0 + b_kof) * SBB + (wn * 32 + b_nof) * 2;

            uint32_t ah[2][4], al[2][4];
            #pragma unroll
            for (int t = 0; t < 2; t++) {
                ldm_x4(dynu + OFF_AHI + a_off + t * 16 * SBB, ah[t]);
                ldm_x4(dynu + OFF_ALO + a_off + t * 16 * SBB, al[t]);
            }
            uint32_t wh[4][2], wl[4][2];
            #pragma unroll
            for (int q = 0; q < 2; q++) {
                uint32_t r0, r1, r2, r3;
                ldm_x4t(dynu + OFF_WHI + b_off + q * 32, r0, r1, r2, r3);
                wh[q * 2][0] = r0;     wh[q * 2][1] = r1;
                wh[q * 2 + 1][0] = r2; wh[q * 2 + 1][1] = r3;
                ldm_x4t(dynu + OFF_WLO + b_off + q * 32, r0, r1, r2, r3);
                wl[q * 2][0] = r0;     wl[q * 2][1] = r1;
                wl[q * 2 + 1][0] = r2; wl[q * 2 + 1][1] = r3;
            }
            #pragma unroll
            for (int t = 0; t < 2; t++)
                #pragma unroll
                for (int j = 0; j < 4; j++) {
                    mma_bf16(acc[t][j], ah[t], wh[j][0], wh[j][1]);
                    mma_bf16(acc[t][j], ah[t], wl[j][0], wl[j][1]);
                    mma_bf16(acc[t][j], al[t], wh[j][0], wh[j][1]);
                }
        }
        __syncthreads();
    }

    // direct STG of accumulators to g_u
    #pragma unroll
    for (int t = 0; t < 2; t++) {
        int m = wm * 32 + t * 16 + (lane >> 2);
        #pragma unroll
        for (int j = 0; j < 4; j++) {
            int n = wn * 32 + j * 8 + (lane & 3) * 2;
            *(float2*)&g_u[((size_t)b0 * TOPK + m) * 128 + n] =
                make_float2(acc[t][j][0], acc[t][j][1]);
            *(float2*)&g_u[((size_t)b0 * TOPK + m + 8) * 128 + n] =
                make_float2(acc[t][j][2], acc[t][j][3]);
        }
    }
}

// ============ kernel 2: pair-phase MLP ============
__global__ __launch_bounds__(NT, 2)
void rpe_pair_kernel(const float* __restrict__ W1,
                     const float* __restrict__ b1,
                     const float* __restrict__ W2,
                     const float* __restrict__ b2,
                     const float* __restrict__ W3,
                     const float* __restrict__ b3,
                     float* __restrict__ out)
{
    __shared__ __align__(16) float sW2[64 * 32];
    __shared__ float s_wdt[64], s_wyi[64], s_wyj[64], s_b1[64];
    __shared__ float s_b2[32], s_W3[32];
    __shared__ float s_b3;
    __shared__ __align__(16) float s_h1b[8][32];

    const int tid  = threadIdx.x;
    const int lane = tid & 31;
    const int wid  = tid >> 5;
    const int b    = blockIdx.x * 8 + wid;

    for (int i = tid; i < 512; i += NT)
        ((float4*)sW2)[i] = ((const float4*)W2)[i];
    if (tid < 64) {
        s_wdt[tid] = W1[768 * 64 + tid];
        s_wyi[tid] = W1[769 * 64 + tid];
        s_wyj[tid] = W1[770 * 64 + tid];
        s_b1[tid]  = b1[tid];
    }
    if (tid < 32) { s_b2[tid] = b2[tid]; s_W3[tid] = W3[tid]; }
    if (tid == 0) s_b3 = b3[0];
    __syncthreads();

    float ur[TOPK][4];
    #pragma unroll
    for (int r = 0; r < TOPK; r++)
        #pragma unroll
        for (int g = 0; g < 4; g++)
            ur[r][g] = g_u[((size_t)b * TOPK + r) * 128 + g * 32 + lane];

    const float tyl = g_ty[(size_t)b * TOPK + (lane & 7)];
    const float ttl = g_tt[(size_t)b * TOPK + (lane & 7)];

    float w2r[64];
    #pragma unroll
    for (int h = 0; h < 64; h++) w2r[h] = sW2[h * 32 + lane];
    const float b2v = s_b2[lane];
    const float w3v = s_W3[lane];
    const float b3v = s_b3;

    float accv = 0.f;   // per-lane: sum over pairs of silu(a2) * yi*yj
    float accb = 0.f;   // sum of yi*yj (replicated across lanes)
    #pragma unroll 4
    for (int p = 0; p < NPAIR; p++) {
        const int i = c_ii[p], j = c_jj[p];
        const float ti = __shfl_sync(0xffffffffu, ttl, i);
        const float tj = __shfl_sync(0xffffffffu, ttl, j);
        const float yi = __shfl_sync(0xffffffffu, tyl, i);
        const float yj = __shfl_sync(0xffffffffu, tyl, j);
        const float dt = ti - tj;

        float pre_lo = ur[i][0] + ur[j][2]
                     + dt * s_wdt[lane] + yi * s_wyi[lane] + yj * s_wyj[lane]
                     + s_b1[lane];
        float pre_hi = ur[i][1] + ur[j][3]
                     + dt * s_wdt[32 + lane] + yi * s_wyi[32 + lane]
                     + yj * s_wyj[32 + lane] + s_b1[32 + lane];
        float h1a = silu(pre_lo);
        float h1b = silu(pre_hi);

        s_h1b[wid][lane] = h1b;
        __syncwarp();

        float s0 = 0.f, s1 = 0.f, s2 = 0.f, s3 = 0.f;
        #pragma unroll
        for (int hh = 0; hh < 32; hh += 4) {
            s0 = fmaf(__shfl_sync(0xffffffffu, h1a, hh),     w2r[hh],     s0);
            s1 = fmaf(__shfl_sync(0xffffffffu, h1a, hh + 1), w2r[hh + 1], s1);
            s2 = fmaf(__shfl_sync(0xffffffffu, h1a, hh + 2), w2r[hh + 2], s2);
            s3 = fmaf(__shfl_sync(0xffffffffu, h1a, hh + 3), w2r[hh + 3], s3);
        }
        #pragma unroll
        for (int c4 = 0; c4 < 8; c4++) {
            float4 hv = *(const float4*)&s_h1b[wid][c4 * 4];
            s0 = fmaf(hv.x, w2r[32 + c4 * 4 + 0], s0);
            s1 = fmaf(hv.y, w2r[32 + c4 * 4 + 1], s1);
            s2 = fmaf(hv.z, w2r[32 + c4 * 4 + 2], s2);
            s3 = fmaf(hv.w, w2r[32 + c4 * 4 + 3], s3);
        }
        float a2 = b2v + (s0 + s1) + (s2 + s3);

        const float yy = yi * yj;
        accv = fmaf(silu(a2), yy, accv);
        accb += yy;
        __syncwarp();
    }

    // single deferred reduction
    float v = accv * w3v;
    #pragma unroll
    for (int off = 16; off > 0; off >>= 1)
        v += __shfl_xor_sync(0xffffffffu, v, off);
    if (lane == 0) out[b] = v + b3v * accb;
}

extern "C" void kernel_launch(void* const* d_in, const int* in_sizes, int n_in,
                              void* d_out, int out_size)
{
    const float* M  = (const float*)d_in[0];
    const float* y  = (const float*)d_in[1];
    const float* ts = (const float*)d_in[2];
    const float* W1 = (const float*)d_in[3];
    const float* b1 = (const float*)d_in[4];
    const float* W2 = (const float*)d_in[5];
    const float* b2 = (const float*)d_in[6];
    const float* W3 = (const float*)d_in[7];
    const float* b3 = (const float*)d_in[8];
    float* out = (float*)d_out;

    w1_prep_kernel<<<96, 512>>>(W1);
    cudaFuncSetAttribute(rpe_gemm_kernel,
                         cudaFuncAttributeMaxDynamicSharedMemorySize, DYN_BYTES);
    rpe_gemm_kernel<<<BB / BPB, NT, DYN_BYTES>>>(M, y, ts);
    rpe_pair_kernel<<<BB / 8, NT>>>(W1, b1, W2, b2, W3, b3, out);
}

// round 7
// speedup vs baseline: 2.4902x; 1.2955x over previous
#include <cuda_runtime.h>
#include <cuda_bf16.h>
#include <cstdint>

#define BB   8192
#define KK   64
#define DD   384
#define TOPK 8
#define NPAIR 28
#define BPB  8        // batches per gemm block
#define NT   256      // gemm: 8 warps
#define SBB  272      // tile row stride bytes (conflict-free ldmatrix)

#define OFF_AHI 0
#define OFF_ALO 17408
#define OFF_WHI 34816
#define OFF_WLO 69632
#define DYN_BYTES 104448

// Pre-converted W1 tiles: [chunk][k][n], row stride 136 bf16 = 272B
__device__ __align__(16) __nv_bfloat16 g_W1H[3][128][136];
__device__ __align__(16) __nv_bfloat16 g_W1L[3][128][136];
// Inter-kernel scratch
__device__ __align__(16) float g_u[BB * TOPK * 128];   // 33.5MB
__device__ float g_ty[BB * TOPK];
__device__ float g_tt[BB * TOPK];

// triu_indices(8, k=1)
__device__ __constant__ int c_ii[NPAIR] =
  {0,0,0,0,0,0,0, 1,1,1,1,1,1, 2,2,2,2,2, 3,3,3,3, 4,4,4, 5,5, 6};
__device__ __constant__ int c_jj[NPAIR] =
  {1,2,3,4,5,6,7, 2,3,4,5,6,7, 3,4,5,6,7, 4,5,6,7, 5,6,7, 6,7, 7};

typedef unsigned long long ull;
#define PACK2(d, lo, hi)  asm("mov.b64 %0, {%1, %2};" : "=l"(d) : "f"(lo), "f"(hi))
#define UNPACK2(lo, hi, s) asm("mov.b64 {%0, %1}, %2;" : "=f"(lo), "=f"(hi) : "l"(s))
#define FMA2(d, a, b, c)  asm("fma.rn.f32x2 %0, %1, %2, %3;" : "=l"(d) : "l"(a), "l"(b), "l"(c))
#define ADD2(d, a, b)     asm("add.rn.f32x2 %0, %1, %2;" : "=l"(d) : "l"(a), "l"(b))

__device__ __forceinline__ uint32_t smem_u32(const void* p) {
    uint32_t a;
    asm("{ .reg .u64 t; cvta.to.shared.u64 t, %1; cvt.u32.u64 %0, t; }"
        : "=r"(a) : "l"(p));
    return a;
}
__device__ __forceinline__ float silu(float x) { return x / (1.0f + __expf(-x)); }

__device__ __forceinline__ void ldm_x4(uint32_t addr, uint32_t* r) {
    asm volatile("ldmatrix.sync.aligned.m8n8.x4.shared.b16 {%0,%1,%2,%3}, [%4];"
        : "=r"(r[0]), "=r"(r[1]), "=r"(r[2]), "=r"(r[3]) : "r"(addr));
}
__device__ __forceinline__ void ldm_x4t(uint32_t addr, uint32_t& r0, uint32_t& r1,
                                        uint32_t& r2, uint32_t& r3) {
    asm volatile("ldmatrix.sync.aligned.m8n8.x4.trans.shared.b16 {%0,%1,%2,%3}, [%4];"
        : "=r"(r0), "=r"(r1), "=r"(r2), "=r"(r3) : "r"(addr));
}
__device__ __forceinline__ void mma_bf16(float* c, const uint32_t* a,
                                         uint32_t b0, uint32_t b1) {
    asm volatile(
        "mma.sync.aligned.m16n8k16.row.col.f32.bf16.bf16.f32 "
        "{%0,%1,%2,%3}, {%4,%5,%6,%7}, {%8,%9}, {%0,%1,%2,%3};"
        : "+f"(c[0]), "+f"(c[1]), "+f"(c[2]), "+f"(c[3])
        : "r"(a[0]), "r"(a[1]), "r"(a[2]), "r"(a[3]), "r"(b0), "r"(b1));
}
__device__ __forceinline__ void split2(float a, float b, uint32_t& hi, uint32_t& lo) {
    asm("cvt.rn.bf16x2.f32 %0, %1, %2;" : "=r"(hi) : "f"(b), "f"(a));
    float ra = __uint_as_float(hi << 16);
    float rb = __uint_as_float(hi & 0xffff0000u);
    float la = a - ra;
    float lb = b - rb;
    asm("cvt.rn.bf16x2.f32 %0, %1, %2;" : "=r"(lo) : "f"(lb), "f"(la));
}
__device__ __forceinline__ void cp_async16(uint32_t dst, const void* src) {
    asm volatile("cp.async.cg.shared.global [%0], [%1], 16;" :: "r"(dst), "l"(src));
}
__device__ __forceinline__ void prefetch_l2(const void* p) {
    asm volatile("prefetch.global.L2 [%0];" :: "l"(p));
}

// ---- prep: convert W1 -> bf16 hi/lo tiles, once ----
__global__ void w1_prep_kernel(const float* __restrict__ W1)
{
    int idx = blockIdx.x * blockDim.x + threadIdx.x;
    int chunk = idx >> 14;
    int k     = (idx >> 7) & 127;
    int n     = idx & 127;
    int g     = ((n >= 64) ? 384 : 0) + chunk * 128 + k;
    float v = W1[(size_t)g * 64 + (n & 63)];
    __nv_bfloat16 h = __float2bfloat16(v);
    __nv_bfloat16 l = __float2bfloat16(v - __bfloat162float(h));
    g_W1H[chunk][k][n] = h;
    g_W1L[chunk][k][n] = l;
}

// ============ kernel 1: topk + layer-1 GEMM -> g_u ============
__global__ __launch_bounds__(NT, 2)
void rpe_gemm_kernel(const float* __restrict__ M,
                     const float* __restrict__ y,
                     const float* __restrict__ ts)
{
    extern __shared__ __align__(128) char dyn[];

    __shared__ __align__(16) float sy[BPB][KK];
    __shared__ __align__(16) float st_[BPB][KK];
    __shared__ int s_idx[BPB][TOPK];

    const int tid  = threadIdx.x;
    const int lane = tid & 31;
    const int wid  = tid >> 5;
    const int b0   = blockIdx.x * BPB;
    const uint32_t dynu = smem_u32(dyn);

    if (tid < 128) {
        ((float4*)sy)[tid]  = ((const float4*)(y  + (size_t)b0 * KK))[tid];
        ((float4*)st_)[tid] = ((const float4*)(ts + (size_t)b0 * KK))[tid];
    }
    __syncthreads();

    // per-warp top-8 (jax.lax.top_k semantics: desc, ties->low idx)
    {
        const int lb = wid;
        unsigned long long k0 =
            ((unsigned long long)__float_as_uint(sy[lb][lane]) << 32) | (unsigned)(63 - lane);
        unsigned long long k1 =
            ((unsigned long long)__float_as_uint(sy[lb][lane + 32]) << 32) | (unsigned)(63 - (lane + 32));
        #pragma unroll
        for (int t = 0; t < TOPK; t++) {
            unsigned long long m = (k0 > k1) ? k0 : k1;
            #pragma unroll
            for (int off = 16; off > 0; off >>= 1) {
                unsigned long long o = __shfl_xor_sync(0xffffffffu, m, off);
                if (o > m) m = o;
            }
            int idx = 63 - (int)(m & 63ull);
            if (idx == lane)      k0 = 0ull;
            if (idx == lane + 32) k1 = 0ull;
            if (lane == 0) {
                s_idx[lb][t] = idx;
                g_ty[(size_t)(b0 + lb) * TOPK + t] = sy[lb][idx];
                g_tt[(size_t)(b0 + lb) * TOPK + t] = st_[lb][idx];
            }
        }
    }
    __syncthreads();

    // precompute per-thread gather byte offsets (fixed across chunks)
    uint32_t goff[8];
    uint32_t soff[8];
    #pragma unroll
    for (int i = 0; i < 8; i++) {
        int idx4 = i * NT + tid;
        int row  = idx4 >> 5;
        int q    = idx4 & 31;
        int lb = row >> 3, slot = row & 7;
        goff[i] = (uint32_t)((((b0 + lb) * KK + s_idx[lb][slot]) * DD + q * 4) * 4);
        soff[i] = (uint32_t)row * SBB + (uint32_t)q * 8;
    }

    const int wm = wid & 1;
    const int wn = wid >> 1;
    const uint32_t a_row = (uint32_t)((lane & 7) + ((lane >> 3) & 1) * 8);
    const uint32_t a_kof = (uint32_t)((lane >> 4) * 8);
    const uint32_t b_kof = (uint32_t)((lane & 7) + ((lane >> 3) & 1) * 8);
    const uint32_t b_nof = (uint32_t)((lane >> 4) * 8);

    float acc[2][4][4];
    #pragma unroll
    for (int t = 0; t < 2; t++)
        #pragma unroll
        for (int j = 0; j < 4; j++)
            #pragma unroll
            for (int r = 0; r < 4; r++) acc[t][j][r] = 0.f;

    for (int chunk = 0; chunk < 3; chunk++) {
        // W copy via cp.async (pre-converted)
        {
            const uint4* srcH = (const uint4*)&g_W1H[chunk][0][0];
            const uint4* srcL = (const uint4*)&g_W1L[chunk][0][0];
            #pragma unroll
            for (int i = tid; i < 2176; i += NT) {
                cp_async16(dynu + OFF_WHI + i * 16, srcH + i);
                cp_async16(dynu + OFF_WLO + i * 16, srcL + i);
            }
            asm volatile("cp.async.commit_group;" ::: "memory");
        }
        // A fill: gather + packed split
        #pragma unroll
        for (int i = 0; i < 8; i++) {
            const float4 v = *(const float4*)((const char*)M + goff[i] + chunk * 512);
            uint2 hp, lp;
            split2(v.x, v.y, hp.x, lp.x);
            split2(v.z, v.w, hp.y, lp.y);
            *(uint2*)(dyn + OFF_AHI + soff[i]) = hp;
            *(uint2*)(dyn + OFF_ALO + soff[i]) = lp;
        }
        // prefetch next chunk's M lines into L2 (1 per 128B line)
        if (chunk < 2 && (tid & 7) == 0) {
            #pragma unroll
            for (int i = 0; i < 8; i++)
                prefetch_l2((const char*)M + goff[i] + (chunk + 1) * 512);
        }
        asm volatile("cp.async.wait_group 0;" ::: "memory");
        __syncthreads();

        // per k16 step: load all frags once, issue the 3 bf16x3 products
        #pragma unroll
        for (int step = 0; step < 8; step++) {
            const uint32_t k0 = (uint32_t)step * 16;
            const uint32_t a_off = (wm * 32 + a_row) * SBB + (k0 + a_kof) * 2;
            const uint32_t b_off = (k0 + b_kof) * SBB + (wn * 32 + b_nof) * 2;

            uint32_t ah[2][4], al[2][4];
            #pragma unroll
            for (int t = 0; t < 2; t++) {
                ldm_x4(dynu + OFF_AHI + a_off + t * 16 * SBB, ah[t]);
                ldm_x4(dynu + OFF_ALO + a_off + t * 16 * SBB, al[t]);
            }
            uint32_t wh[4][2], wl[4][2];
            #pragma unroll
            for (int q = 0; q < 2; q++) {
                uint32_t r0, r1, r2, r3;
                ldm_x4t(dynu + OFF_WHI + b_off + q * 32, r0, r1, r2, r3);
                wh[q * 2][0] = r0;     wh[q * 2][1] = r1;
                wh[q * 2 + 1][0] = r2; wh[q * 2 + 1][1] = r3;
                ldm_x4t(dynu + OFF_WLO + b_off + q * 32, r0, r1, r2, r3);
                wl[q * 2][0] = r0;     wl[q * 2][1] = r1;
                wl[q * 2 + 1][0] = r2; wl[q * 2 + 1][1] = r3;
            }
            #pragma unroll
            for (int t = 0; t < 2; t++)
                #pragma unroll
                for (int j = 0; j < 4; j++) {
                    mma_bf16(acc[t][j], ah[t], wh[j][0], wh[j][1]);
                    mma_bf16(acc[t][j], ah[t], wl[j][0], wl[j][1]);
                    mma_bf16(acc[t][j], al[t], wh[j][0], wh[j][1]);
                }
        }
        __syncthreads();
    }

    // direct STG of accumulators to g_u
    #pragma unroll
    for (int t = 0; t < 2; t++) {
        int m = wm * 32 + t * 16 + (lane >> 2);
        #pragma unroll
        for (int j = 0; j < 4; j++) {
            int n = wn * 32 + j * 8 + (lane & 3) * 2;
            *(float2*)&g_u[((size_t)b0 * TOPK + m) * 128 + n] =
                make_float2(acc[t][j][0], acc[t][j][1]);
            *(float2*)&g_u[((size_t)b0 * TOPK + m + 8) * 128 + n] =
                make_float2(acc[t][j][2], acc[t][j][3]);
        }
    }
}

// ============ kernel 2: pair-phase MLP (f32x2 packed) ============
__global__ __launch_bounds__(128, 3)
void rpe_pair_kernel(const float* __restrict__ W1,
                     const float* __restrict__ b1,
                     const float* __restrict__ W2,
                     const float* __restrict__ b2,
                     const float* __restrict__ W3,
                     const float* __restrict__ b3,
                     float* __restrict__ out)
{
    __shared__ __align__(16) float s_h1[4][64];

    const int tid  = threadIdx.x;
    const int lane = tid & 31;
    const int wid  = tid >> 5;
    const int b    = blockIdx.x * 4 + wid;

    // packed weights / constants (all loads L2-hot after first wave)
    ull w2p[32];
    #pragma unroll
    for (int i = 0; i < 32; i++)
        PACK2(w2p[i], W2[(2 * i) * 32 + lane], W2[(2 * i + 1) * 32 + lane]);
    ull wdt2, wyi2, wyj2, b1_2;
    PACK2(wdt2, W1[768 * 64 + lane], W1[768 * 64 + 32 + lane]);
    PACK2(wyi2, W1[769 * 64 + lane], W1[769 * 64 + 32 + lane]);
    PACK2(wyj2, W1[770 * 64 + lane], W1[770 * 64 + 32 + lane]);
    PACK2(b1_2, b1[lane], b1[32 + lane]);
    const float b2v = b2[lane];
    const float w3v = W3[lane];
    const float b3v = b3[0];

    // packed u: upi[r] = {u[r][lane], u[r][32+lane]}; upj[r] = {u[r][64+lane], u[r][96+lane]}
    ull upi[TOPK], upj[TOPK];
    #pragma unroll
    for (int r = 0; r < TOPK; r++) {
        const float* ur = &g_u[((size_t)b * TOPK + r) * 128];
        PACK2(upi[r], ur[lane], ur[32 + lane]);
        PACK2(upj[r], ur[64 + lane], ur[96 + lane]);
    }

    const float tyl = g_ty[(size_t)b * TOPK + (lane & 7)];
    const float ttl = g_tt[(size_t)b * TOPK + (lane & 7)];

    float accv = 0.f;   // per-lane: sum over pairs of silu(a2)*yi*yj
    float accb = 0.f;   // sum of yi*yj
    #pragma unroll 4
    for (int p = 0; p < NPAIR; p++) {
        const int i = c_ii[p], j = c_jj[p];
        const float ti = __shfl_sync(0xffffffffu, ttl, i);
        const float tj = __shfl_sync(0xffffffffu, ttl, j);
        const float yi = __shfl_sync(0xffffffffu, tyl, i);
        const float yj = __shfl_sync(0xffffffffu, tyl, j);
        const float dt = ti - tj;

        ull dt2, yi2, yj2;
        PACK2(dt2, dt, dt);
        PACK2(yi2, yi, yi);
        PACK2(yj2, yj, yj);

        // pre2 = {pre_lo, pre_hi}
        ull pre2;
        ADD2(pre2, upi[i], upj[j]);
        FMA2(pre2, dt2, wdt2, pre2);
        FMA2(pre2, yi2, wyi2, pre2);
        FMA2(pre2, yj2, wyj2, pre2);
        ADD2(pre2, pre2, b1_2);

        float pre_lo, pre_hi;
        UNPACK2(pre_lo, pre_hi, pre2);
        s_h1[wid][lane]      = silu(pre_lo);
        s_h1[wid][32 + lane] = silu(pre_hi);
        __syncwarp();

        // layer 2: 64 h values as 32 packed pairs (LDS.128 broadcast)
        ull a0 = 0ull, a1 = 0ull, a2p = 0ull, a3 = 0ull;
        const ulonglong2* hq = (const ulonglong2*)&s_h1[wid][0];
        #pragma unroll
        for (int c = 0; c < 16; c += 2) {
            ulonglong2 h0 = hq[c];
            ulonglong2 h1 = hq[c + 1];
            FMA2(a0, h0.x, w2p[2 * c],     a0);
            FMA2(a1, h0.y, w2p[2 * c + 1], a1);
            FMA2(a2p, h1.x, w2p[2 * c + 2], a2p);
            FMA2(a3, h1.y, w2p[2 * c + 3], a3);
        }
        float f0, f1, f2, f3, f4, f5, f6, f7;
        UNPACK2(f0, f1, a0);
        UNPACK2(f2, f3, a1);
        UNPACK2(f4, f5, a2p);
        UNPACK2(f6, f7, a3);
        float a2 = b2v + ((f0 + f1) + (f2 + f3)) + ((f4 + f5) + (f6 + f7));

        const float yy = yi * yj;
        accv = fmaf(silu(a2), yy, accv);
        accb += yy;
        __syncwarp();
    }

    float v = accv * w3v;
    #pragma unroll
    for (int off = 16; off > 0; off >>= 1)
        v += __shfl_xor_sync(0xffffffffu, v, off);
    if (lane == 0) out[b] = v + b3v * accb;
}

extern "C" void kernel_launch(void* const* d_in, const int* in_sizes, int n_in,
                              void* d_out, int out_size)
{
    const float* M  = (const float*)d_in[0];
    const float* y  = (const float*)d_in[1];
    const float* ts = (const float*)d_in[2];
    const float* W1 = (const float*)d_in[3];
    const float* b1 = (const float*)d_in[4];
    const float* W2 = (const float*)d_in[5];
    const float* b2 = (const float*)d_in[6];
    const float* W3 = (const float*)d_in[7];
    const float* b3 = (const float*)d_in[8];
    float* out = (float*)d_out;

    w1_prep_kernel<<<96, 512>>>(W1);
    cudaFuncSetAttribute(rpe_gemm_kernel,
                         cudaFuncAttributeMaxDynamicSharedMemorySize, DYN_BYTES);
    rpe_gemm_kernel<<<BB / BPB, NT, DYN_BYTES>>>(M, y, ts);
    rpe_pair_kernel<<<BB / 4, 128>>>(W1, b1, W2, b2, W3, b3, out);
}